// round 17
// baseline (speedup 1.0000x reference)
#include <cuda_runtime.h>
#include <cstdint>

// ===========================================================================
// SelfAttention via mma.sync tf32 — Round 15: flash = R13 (best, untouched).
// GEMM: weights pre-rounded to tf32 (prepass) -> no B-side cvt in hot loop;
// K-chunk 32 -> 64 (half the syncs/pipeline drains). A-side cvt kept (raw A).
//   K0: round w_qkv, w_out -> tf32
//   K1: mma_gemm   x @ w_qkv_r          -> g_qkv  [16384 x 768]
//   K2: mma_flash  attention            -> g_attn [16384 x 256]
//   K1: mma_gemm   g_attn @ w_out_r + b -> out    [16384 x 512]
// ===========================================================================

#define NTOK   16384
#define DMODEL 512
#define INNER  256
#define QKVN   768
#define HEADS  4
#define DH     64
#define TSEQ   2048

__device__ float g_qkv[NTOK * QKVN];       // 48 MB
__device__ float g_attn[NTOK * INNER];     // 16 MB
__device__ float g_wqkv_r[DMODEL * QKVN];  // 1.5 MB
__device__ float g_wout_r[INNER * DMODEL]; // 0.5 MB

__device__ __forceinline__ uint32_t smem_u32(const void* p) {
    uint32_t a;
    asm("{ .reg .u64 t; cvta.to.shared.u64 t, %1; cvt.u32.u64 %0, t; }"
        : "=r"(a) : "l"(p));
    return a;
}
__device__ __forceinline__ uint32_t f2tf32(float x) {
    uint32_t r;
    asm("cvt.rna.tf32.f32 %0, %1;" : "=r"(r) : "f"(x));
    return r;
}
__device__ __forceinline__ uint32_t tf32_w(uint32_t bits) {
    return f2tf32(__uint_as_float(bits));
}
__device__ __forceinline__ float ex2f(float x) {
    float r;
    asm("ex2.approx.f32 %0, %1;" : "=f"(r) : "f"(x));
    return r;
}
__device__ __forceinline__ void cp_async16(uint32_t saddr, const void* gptr) {
    asm volatile("cp.async.ca.shared.global [%0], [%1], 16;"
                 :: "r"(saddr), "l"(gptr));
}
#define CP_COMMIT() asm volatile("cp.async.commit_group;" ::: "memory")
#define CP_WAIT0()  asm volatile("cp.async.wait_group 0;" ::: "memory")

__device__ __forceinline__ void ldsm_x4(uint32_t& r0, uint32_t& r1,
                                        uint32_t& r2, uint32_t& r3,
                                        uint32_t saddr) {
    asm volatile("ldmatrix.sync.aligned.m8n8.x4.shared.b16 {%0,%1,%2,%3}, [%4];"
                 : "=r"(r0), "=r"(r1), "=r"(r2), "=r"(r3) : "r"(saddr));
}

__device__ __forceinline__ void mma_tf32(float* c, const uint32_t* a,
                                         uint32_t b0, uint32_t b1) {
    asm volatile(
        "mma.sync.aligned.m16n8k8.row.col.f32.tf32.tf32.f32 "
        "{%0,%1,%2,%3}, {%4,%5,%6,%7}, {%8,%9}, {%0,%1,%2,%3};"
        : "+f"(c[0]), "+f"(c[1]), "+f"(c[2]), "+f"(c[3])
        : "r"(a[0]), "r"(a[1]), "r"(a[2]), "r"(a[3]), "r"(b0), "r"(b1));
}

// ------------------------- K0: tf32 rounding prepass ------------------------
__global__ void round_tf32_kernel(const float* __restrict__ src,
                                  float* __restrict__ dst, int n4) {
    int i = blockIdx.x * blockDim.x + threadIdx.x;
    if (i < n4) {
        float4 v = reinterpret_cast<const float4*>(src)[i];
        v.x = __uint_as_float(f2tf32(v.x));
        v.y = __uint_as_float(f2tf32(v.y));
        v.z = __uint_as_float(f2tf32(v.z));
        v.w = __uint_as_float(f2tf32(v.w));
        reinterpret_cast<float4*>(dst)[i] = v;
    }
}

// ---------------------------------------------------------------------------
// GEMM: C = A @ B (+bias). 256 thr, CTA tile 256x128, K-CHUNK 64, warp tile
// 64x64, cp.async double buffer. B is pre-rounded tf32 (no cvt); A cvt'd at
// fragment load; A-frags via LDSM.x4.
// AP=68 (==4 mod 32), BP=136 (==8 mod 32): fills + frags conflict-free.
// ---------------------------------------------------------------------------
#define AP 68
#define BP 136
#define GM_BS    (256 * AP)              // 17408 words
#define GM_WORDS (GM_BS + 64 * BP)       // one buffer: 26112 words
#define GM_BYTES (2 * GM_WORDS * 4)      // 208896 B

__global__ __launch_bounds__(256, 1) void mma_gemm_kernel(
    const float* __restrict__ A, const float* __restrict__ B,
    const float* __restrict__ bias, float* __restrict__ C,
    int M, int N, int K)
{
    extern __shared__ uint32_t sm[];
    const uint32_t smb = smem_u32(sm);

    const int tid = threadIdx.x;
    const int wid = tid >> 5, lane = tid & 31;
    const int g = lane >> 2, tg = lane & 3;
    const int wm = wid & 3, wn = wid >> 2;
    const int row0 = blockIdx.y * 256, col0 = blockIdx.x * 128;

    const int lmat = lane >> 3, lrow = lane & 7;
    const int afix = ((lmat & 1) * 8 + lrow) * AP + (lmat >> 1) * 4;

    // per-thread load coords: A 256x64 (16 float4), B 64x128 (8 float4)
    int ar[16], ac[16], br[8], bc[8];
    #pragma unroll
    for (int i = 0; i < 16; i++) {
        int flat = tid * 4 + i * 1024;
        ar[i] = flat >> 6; ac[i] = flat & 63;
    }
    #pragma unroll
    for (int i = 0; i < 8; i++) {
        int flat = tid * 4 + i * 1024;
        br[i] = flat >> 7; bc[i] = flat & 127;
    }

    float c[4][8][4];
    #pragma unroll
    for (int mt = 0; mt < 4; mt++)
        #pragma unroll
        for (int nt = 0; nt < 8; nt++)
            #pragma unroll
            for (int j = 0; j < 4; j++) c[mt][nt][j] = 0.f;

    const int nchunks = K >> 6;

    #pragma unroll
    for (int i = 0; i < 16; i++)
        cp_async16(smb + (ar[i] * AP + ac[i]) * 4,
                   A + (size_t)(row0 + ar[i]) * K + ac[i]);
    #pragma unroll
    for (int i = 0; i < 8; i++)
        cp_async16(smb + (GM_BS + br[i] * BP + bc[i]) * 4,
                   B + (size_t)br[i] * N + col0 + bc[i]);
    CP_COMMIT();
    CP_WAIT0();
    __syncthreads();

    for (int ch = 0; ch < nchunks; ch++) {
        const int cur = ch & 1;
        const uint32_t sA = smb + cur * GM_WORDS * 4;
        const uint32_t* Bs = sm + cur * GM_WORDS + GM_BS;

        if (ch + 1 < nchunks) {
            const int nxt = cur ^ 1;
            const uint32_t nb = smb + nxt * GM_WORDS * 4;
            int k0 = (ch + 1) * 64;
            #pragma unroll
            for (int i = 0; i < 16; i++)
                cp_async16(nb + (ar[i] * AP + ac[i]) * 4,
                           A + (size_t)(row0 + ar[i]) * K + k0 + ac[i]);
            #pragma unroll
            for (int i = 0; i < 8; i++)
                cp_async16(nb + (GM_BS + br[i] * BP + bc[i]) * 4,
                           B + (size_t)(k0 + br[i]) * N + col0 + bc[i]);
            CP_COMMIT();
        }

        #pragma unroll
        for (int ks = 0; ks < 8; ks++) {
            uint32_t a[4][4], b[8][2];
            #pragma unroll
            for (int mt = 0; mt < 4; mt++) {
                uint32_t addr = sA + (((wm * 64 + mt * 16) * AP) + ks * 8 + afix) * 4;
                ldsm_x4(a[mt][0], a[mt][1], a[mt][2], a[mt][3], addr);
                a[mt][0] = tf32_w(a[mt][0]);
                a[mt][1] = tf32_w(a[mt][1]);
                a[mt][2] = tf32_w(a[mt][2]);
                a[mt][3] = tf32_w(a[mt][3]);
            }
            #pragma unroll
            for (int nt = 0; nt < 8; nt++) {
                int bb = (ks * 8 + tg) * BP + wn * 64 + nt * 8 + g;
                b[nt][0] = Bs[bb];               // pre-rounded: no cvt
                b[nt][1] = Bs[bb + 4 * BP];
            }
            #pragma unroll
            for (int mt = 0; mt < 4; mt++)
                #pragma unroll
                for (int nt = 0; nt < 8; nt++)
                    mma_tf32(c[mt][nt], a[mt], b[nt][0], b[nt][1]);
        }

        if (ch + 1 < nchunks) {
            CP_WAIT0();
            __syncthreads();
        }
    }

    #pragma unroll
    for (int mt = 0; mt < 4; mt++) {
        int r = row0 + wm * 64 + mt * 16 + g;
        #pragma unroll
        for (int nt = 0; nt < 8; nt++) {
            int cc = col0 + wn * 64 + nt * 8 + 2 * tg;
            float bx = 0.f, by = 0.f;
            if (bias) { bx = bias[cc]; by = bias[cc + 1]; }
            float2 v0 = make_float2(c[mt][nt][0] + bx, c[mt][nt][1] + by);
            float2 v1 = make_float2(c[mt][nt][2] + bx, c[mt][nt][3] + by);
            *reinterpret_cast<float2*>(C + (size_t)r * N + cc) = v0;
            *reinterpret_cast<float2*>(C + (size_t)(r + 8) * N + cc) = v1;
        }
    }
}

// ---------------------------------------------------------------------------
// Flash attention (R13 best, UNCHANGED): flat softmax, 128 thr / 4 warps,
// 128 q-rows/CTA, 2 CTAs/SM; kv tiles 64; K/V b-frags shared across mtiles;
// Q frags register-resident; K b-frags + P a-frags via LDSM.x4; ex2.approx.
// Pitches: Qs/Ks/Ps 68 (==4 mod 32), Vs 72 (==8). smem = 105472 B.
// ---------------------------------------------------------------------------
#define QP 68
#define VP 72
#define PP 68
#define FA_KS    (128 * QP)
#define FA_VS    (FA_KS + 64 * QP)
#define FA_PS    (FA_VS + 64 * VP)
#define FA_WORDS (FA_PS + 128 * PP)
#define FA_BYTES (FA_WORDS * 4)          // 105472 B

#define QSCALE 0.180336880f   // 0.125 * log2(e)

__global__ __launch_bounds__(128, 2) void mma_flash_kernel(
    const float* __restrict__ qkv, float* __restrict__ attn)
{
    extern __shared__ uint32_t sm[];
    const uint32_t smb = smem_u32(sm);
    uint32_t* Qs = sm;
    uint32_t* Ks = sm + FA_KS;
    uint32_t* Vs = sm + FA_VS;
    uint32_t* Ps = sm + FA_PS;
    const uint32_t Ks_b = smb + FA_KS * 4;
    const uint32_t Ps_b = smb + FA_PS * 4;

    const int tid = threadIdx.x;
    const int wid = tid >> 5, lane = tid & 31;
    const int g = lane >> 2, tg = lane & 3;
    const int qt = blockIdx.x, h = blockIdx.y, bb = blockIdx.z;
    const int tok_q0 = bb * TSEQ + qt * 128;
    const int wb0 = wid * 32, wb1 = wid * 32 + 16;

    const int lmat = lane >> 3, lrow = lane & 7;
    const int afixP = ((lmat & 1) * 8 + lrow) * PP + (lmat >> 1) * 4;
    const int bfixK = ((lmat >> 1) * 8 + lrow) * QP + (lmat & 1) * 4;

    #pragma unroll
    for (int i = 0; i < 16; i++) {
        int flat = tid * 4 + i * 512;
        int r = flat >> 6, cc = flat & 63;
        float4 v = *reinterpret_cast<const float4*>(
            qkv + (size_t)(tok_q0 + r) * QKVN + h * DH + cc);
        uint4 w;
        w.x = f2tf32(v.x * QSCALE);
        w.y = f2tf32(v.y * QSCALE);
        w.z = f2tf32(v.z * QSCALE);
        w.w = f2tf32(v.w * QSCALE);
        *reinterpret_cast<uint4*>(&Qs[r * QP + cc]) = w;
    }
    __syncthreads();

    uint32_t qa[2][8][4];
    #pragma unroll
    for (int ks = 0; ks < 8; ks++) {
        ldsm_x4(qa[0][ks][0], qa[0][ks][1], qa[0][ks][2], qa[0][ks][3],
                smb + (wb0 * QP + ks * 8 + afixP) * 4);
        ldsm_x4(qa[1][ks][0], qa[1][ks][1], qa[1][ks][2], qa[1][ks][3],
                smb + (wb1 * QP + ks * 8 + afixP) * 4);
    }

    float ps[2][2] = {{0.f, 0.f}, {0.f, 0.f}};
    float o[2][8][4];
    #pragma unroll
    for (int mt = 0; mt < 2; mt++)
        #pragma unroll
        for (int nt = 0; nt < 8; nt++)
            #pragma unroll
            for (int j = 0; j < 4; j++) o[mt][nt][j] = 0.f;

    for (int kt = 0; kt < TSEQ / 64; kt++) {
        const int tok_k0 = bb * TSEQ + kt * 64;
        __syncthreads();
        #pragma unroll
        for (int i = 0; i < 8; i++) {
            int flat = tid * 4 + i * 512;
            int r = flat >> 6, cc = flat & 63;
            size_t base = (size_t)(tok_k0 + r) * QKVN + h * DH + cc;
            float4 kv4 = *reinterpret_cast<const float4*>(qkv + base + INNER);
            float4 vv4 = *reinterpret_cast<const float4*>(qkv + base + 2 * INNER);
            uint4 kw, vw;
            kw.x = f2tf32(kv4.x); kw.y = f2tf32(kv4.y);
            kw.z = f2tf32(kv4.z); kw.w = f2tf32(kv4.w);
            vw.x = f2tf32(vv4.x); vw.y = f2tf32(vv4.y);
            vw.z = f2tf32(vv4.z); vw.w = f2tf32(vv4.w);
            *reinterpret_cast<uint4*>(&Ks[r * QP + cc]) = kw;
            *reinterpret_cast<uint4*>(&Vs[r * VP + cc]) = vw;
        }
        __syncthreads();

        float s0[8][4], s1[8][4];
        #pragma unroll
        for (int nt = 0; nt < 8; nt++)
            #pragma unroll
            for (int j = 0; j < 4; j++) { s0[nt][j] = 0.f; s1[nt][j] = 0.f; }
        #pragma unroll
        for (int ks = 0; ks < 8; ks++) {
            #pragma unroll
            for (int j = 0; j < 4; j++) {
                uint32_t kb[4];
                ldsm_x4(kb[0], kb[1], kb[2], kb[3],
                        Ks_b + (j * 16 * QP + ks * 8 + bfixK) * 4);
                mma_tf32(s0[2 * j],     qa[0][ks], kb[0], kb[1]);
                mma_tf32(s1[2 * j],     qa[1][ks], kb[0], kb[1]);
                mma_tf32(s0[2 * j + 1], qa[0][ks], kb[2], kb[3]);
                mma_tf32(s1[2 * j + 1], qa[1][ks], kb[2], kb[3]);
            }
        }

        #pragma unroll
        for (int mt = 0; mt < 2; mt++) {
            float (*s)[4] = mt ? s1 : s0;
            float sum0 = 0.f, sum1 = 0.f;
            #pragma unroll
            for (int nt = 0; nt < 8; nt++) {
                s[nt][0] = ex2f(s[nt][0]);
                s[nt][1] = ex2f(s[nt][1]);
                s[nt][2] = ex2f(s[nt][2]);
                s[nt][3] = ex2f(s[nt][3]);
                sum0 += s[nt][0] + s[nt][1];
                sum1 += s[nt][2] + s[nt][3];
            }
            ps[mt][0] += sum0;
            ps[mt][1] += sum1;
            const int wb = mt ? wb1 : wb0;
            int r0 = (wb + g) * PP, r1 = (wb + g + 8) * PP;
            #pragma unroll
            for (int nt = 0; nt < 8; nt++) {
                int cc = nt * 8 + 2 * tg;
                uint2 p0, p1;
                p0.x = f2tf32(s[nt][0]); p0.y = f2tf32(s[nt][1]);
                p1.x = f2tf32(s[nt][2]); p1.y = f2tf32(s[nt][3]);
                *reinterpret_cast<uint2*>(&Ps[r0 + cc]) = p0;
                *reinterpret_cast<uint2*>(&Ps[r1 + cc]) = p1;
            }
        }
        __syncwarp();

        #pragma unroll
        for (int ks = 0; ks < 8; ks++) {
            uint32_t a0[4], a1[4];
            ldsm_x4(a0[0], a0[1], a0[2], a0[3],
                    Ps_b + (wb0 * PP + ks * 8 + afixP) * 4);
            ldsm_x4(a1[0], a1[1], a1[2], a1[3],
                    Ps_b + (wb1 * PP + ks * 8 + afixP) * 4);
            #pragma unroll
            for (int nt = 0; nt < 8; nt++) {
                int bidx = (ks * 8 + tg) * VP + nt * 8 + g;
                uint32_t vb0 = Vs[bidx], vb1 = Vs[bidx + 4 * VP];
                mma_tf32(o[0][nt], a0, vb0, vb1);
                mma_tf32(o[1][nt], a1, vb0, vb1);
            }
        }
        __syncwarp();
    }

    #pragma unroll
    for (int mt = 0; mt < 2; mt++) {
        float l0 = ps[mt][0], l1 = ps[mt][1];
        l0 += __shfl_xor_sync(0xffffffffu, l0, 1);
        l0 += __shfl_xor_sync(0xffffffffu, l0, 2);
        l1 += __shfl_xor_sync(0xffffffffu, l1, 1);
        l1 += __shfl_xor_sync(0xffffffffu, l1, 2);
        const float li0 = 1.f / l0, li1 = 1.f / l1;
        const int r = tok_q0 + wid * 32 + mt * 16 + g;
        #pragma unroll
        for (int nt = 0; nt < 8; nt++) {
            int cc = h * DH + nt * 8 + 2 * tg;
            float2 v0 = make_float2(o[mt][nt][0] * li0, o[mt][nt][1] * li0);
            float2 v1 = make_float2(o[mt][nt][2] * li1, o[mt][nt][3] * li1);
            *reinterpret_cast<float2*>(attn + (size_t)r * INNER + cc) = v0;
            *reinterpret_cast<float2*>(attn + (size_t)(r + 8) * INNER + cc) = v1;
        }
    }
}

// ---------------------------------------------------------------------------
extern "C" void kernel_launch(void* const* d_in, const int* in_sizes, int n_in,
                              void* d_out, int out_size)
{
    (void)in_sizes; (void)n_in; (void)out_size;
    const float* x     = (const float*)d_in[0];
    const float* w_qkv = (const float*)d_in[1];
    const float* w_out = (const float*)d_in[2];
    const float* b_out = (const float*)d_in[3];
    float* out = (float*)d_out;

    float *qkv_p, *attn_p, *wqkv_r, *wout_r;
    cudaGetSymbolAddress((void**)&qkv_p,  g_qkv);
    cudaGetSymbolAddress((void**)&attn_p, g_attn);
    cudaGetSymbolAddress((void**)&wqkv_r, g_wqkv_r);
    cudaGetSymbolAddress((void**)&wout_r, g_wout_r);

    cudaFuncSetAttribute(mma_gemm_kernel,
        cudaFuncAttributeMaxDynamicSharedMemorySize, GM_BYTES);
    cudaFuncSetAttribute(mma_flash_kernel,
        cudaFuncAttributeMaxDynamicSharedMemorySize, FA_BYTES);

    // K0: round weights to tf32 once (B-side cvt removed from hot loops)
    round_tf32_kernel<<<(DMODEL * QKVN / 4 + 255) / 256, 256>>>(
        w_qkv, wqkv_r, DMODEL * QKVN / 4);
    round_tf32_kernel<<<(INNER * DMODEL / 4 + 255) / 256, 256>>>(
        w_out, wout_r, INNER * DMODEL / 4);

    // QKV projection: [16384,512] @ [512,768]
    mma_gemm_kernel<<<dim3(QKVN / 128, NTOK / 256), 256, GM_BYTES>>>(
        x, wqkv_r, nullptr, qkv_p, NTOK, QKVN, DMODEL);
    // attention: 128 q-rows per CTA, 2 CTAs/SM
    mma_flash_kernel<<<dim3(TSEQ / 128, HEADS, 8), 128, FA_BYTES>>>(
        qkv_p, attn_p);
    // output projection: [16384,256] @ [256,512] + bias
    mma_gemm_kernel<<<dim3(DMODEL / 128, NTOK / 256), 256, GM_BYTES>>>(
        attn_p, wout_r, b_out, out, NTOK, DMODEL, INNER);
}